// round 11
// baseline (speedup 1.0000x reference)
#include <cuda_runtime.h>
#include <cuda_bf16.h>
#include <cstdint>

#define LRELU_SLOPE 0.2f

// Scratch: [dir][graph(256)][node(64)][ch(64)]
__device__ float g_feat[2][256 * 64 * 64];
__device__ float g_gout[2][256 * 64 * 64];

__device__ __forceinline__ float leaky(float v) { return v >= 0.f ? v : LRELU_SLOPE * v; }

// ---- packed f32x2 helpers ----
__device__ __forceinline__ uint64_t pk2(float x, float y) {
    uint64_t r; asm("mov.b64 %0, {%1, %2};" : "=l"(r) : "f"(x), "f"(y)); return r;
}
__device__ __forceinline__ void upk2(uint64_t v, float& x, float& y) {
    asm("mov.b64 {%0, %1}, %2;" : "=f"(x), "=f"(y) : "l"(v));
}
__device__ __forceinline__ uint64_t fma2(uint64_t a, uint64_t b, uint64_t c) {
    uint64_t d; asm("fma.rn.f32x2 %0, %1, %2, %3;" : "=l"(d) : "l"(a), "l"(b), "l"(c)); return d;
}

__device__ __forceinline__ uint32_t smem_u32(const void* p) {
    uint32_t a;
    asm("{ .reg .u64 t; cvta.to.shared.u64 t, %1; cvt.u32.u64 %0, t; }" : "=r"(a) : "l"(p));
    return a;
}
#define SW128(o) ((o) ^ (((o) >> 3) & 0x70))

__device__ __forceinline__ void ldsm4(uint32_t r[4], uint32_t addr) {
    asm volatile("ldmatrix.sync.aligned.m8n8.x4.shared.b16 {%0,%1,%2,%3}, [%4];"
                 : "=r"(r[0]), "=r"(r[1]), "=r"(r[2]), "=r"(r[3]) : "r"(addr));
}
__device__ __forceinline__ void mma16816(float c[4], const uint32_t a[4], uint32_t b0, uint32_t b1) {
    asm volatile(
        "mma.sync.aligned.m16n8k16.row.col.f32.bf16.bf16.f32 "
        "{%0,%1,%2,%3}, {%4,%5,%6,%7}, {%8,%9}, {%0,%1,%2,%3};"
        : "+f"(c[0]), "+f"(c[1]), "+f"(c[2]), "+f"(c[3])
        : "r"(a[0]), "r"(a[1]), "r"(a[2]), "r"(a[3]), "r"(b0), "r"(b1));
}

__device__ __forceinline__ void split_store16(char* base_hi, char* base_lo, uint32_t off, float v) {
    __nv_bfloat16 h = __float2bfloat16(v);
    __nv_bfloat16 l = __float2bfloat16(v - __bfloat162float(h));
    *(__nv_bfloat16*)(base_hi + off) = h;
    *(__nv_bfloat16*)(base_lo + off) = l;
}

// Shared conv GEMM core: C[128 oc][64 w] = A[128 oc][128 c] * B[64 w][128 c]
// A/B in bf16 hi/lo, 2 K-tiles of 64 c each (128B SW128 rows). 3-term split.
__device__ __forceinline__ void conv_mma(uint32_t smb,
                                         uint32_t oAH, uint32_t oAL,
                                         uint32_t oBH, uint32_t oBL,
                                         int wid, int lane, float c[8][4])
{
#pragma unroll
    for (int nt = 0; nt < 8; nt++)
#pragma unroll
        for (int j = 0; j < 4; j++) c[nt][j] = 0.f;

    const int warpM = wid * 16;
    const uint32_t aRow = warpM + (lane & 15);
    const uint32_t aK8 = (lane >> 4) * 8;
    const int q = lane >> 3;
    const uint32_t bRow = (lane & 7) + ((q >> 1) * 8);
    const uint32_t bK8 = (q & 1) * 8;

#pragma unroll
    for (int ks = 0; ks < 8; ks++) {
        const uint32_t tA = (ks >> 2) * 16384u;
        const uint32_t tB = (ks >> 2) * 8192u;
        const int kin = ks & 3;
        const uint32_t ao = tA + SW128(aRow * 128 + (kin * 16 + aK8) * 2);
        uint32_t aH[4], aL[4];
        ldsm4(aH, smb + oAH + ao);
        ldsm4(aL, smb + oAL + ao);
#pragma unroll
        for (int nt2 = 0; nt2 < 4; nt2++) {
            const uint32_t bo = tB + SW128((nt2 * 16 + bRow) * 128 + (kin * 16 + bK8) * 2);
            uint32_t bH[4], bL[4];
            ldsm4(bH, smb + oBH + bo);
            ldsm4(bL, smb + oBL + bo);
            mma16816(c[nt2 * 2 + 0], aH, bH[0], bH[1]);
            mma16816(c[nt2 * 2 + 1], aH, bH[2], bH[3]);
            mma16816(c[nt2 * 2 + 0], aH, bL[0], bL[1]);
            mma16816(c[nt2 * 2 + 1], aH, bL[2], bL[3]);
            mma16816(c[nt2 * 2 + 0], aL, bH[0], bH[1]);
            mma16816(c[nt2 * 2 + 1], aL, bH[2], bH[3]);
        }
    }
}

// ============================================================================
// Kernel 1: LayerNorm + 1x1 conv (MMA) + leaky + strip split
// Smem: XS(fp32 [128][64]) 0..32768 aliased by SC(fp32 [64][132]) 0..33792,
//       MU 33792, RS 34048, AH 34816(32K), AL 67584(32K), BH 100352(16K), BL 116736(16K)
// ============================================================================
#define PRE_XS 0u
#define PRE_SC 0u
#define PRE_MU 33792u
#define PRE_RS 34048u
#define PRE_AH 34816u
#define PRE_AL 67584u
#define PRE_BH 100352u
#define PRE_BL 116736u
#define PRE_SMEM 133120u

__global__ __launch_bounds__(256) void k_pre(
    const float* __restrict__ x, const float* __restrict__ norm_w,
    const float* __restrict__ norm_b, const float* __restrict__ conv_w,
    const float* __restrict__ conv_b)
{
    extern __shared__ __align__(1024) char smp[];
    const uint32_t smb = smem_u32(smp);
    float* xs = (float*)(smp + PRE_XS);
    float* sC = (float*)(smp + PRE_SC);
    float* mu = (float*)(smp + PRE_MU);
    float* rs = (float*)(smp + PRE_RS);
    const int tid = threadIdx.x;
    const int wid = tid >> 5, lane = tid & 31;
    const int b = blockIdx.x >> 6, h = blockIdx.x & 63;
    const float* xblk = x + (size_t)b * 128 * 4096 + h * 64;

    for (int i = tid; i < 128 * 64; i += 256) {
        int c = i >> 6, w = i & 63;
        xs[i] = xblk[c * 4096 + w];
    }
    // stage conv_w as bf16 hi/lo A operand (2 K-tiles)
    for (int i = tid; i < 16384; i += 256) {
        int oc = i >> 7, cc = i & 127;
        float v = conv_w[i];
        uint32_t off = ((uint32_t)(cc >> 6)) * 16384u + SW128((uint32_t)(oc * 128 + (cc & 63) * 2));
        split_store16(smp + PRE_AH, smp + PRE_AL, off, v);
    }
    __syncthreads();
    if (tid < 64) {
        float s = 0.f, s2 = 0.f;
#pragma unroll 8
        for (int c = 0; c < 128; c++) { float v = xs[c * 64 + tid]; s += v; s2 += v * v; }
        float m = s * 0.0078125f;
        float var = s2 * 0.0078125f - m * m;
        mu[tid] = m; rs[tid] = rsqrtf(var + 1e-5f);
    }
    __syncthreads();
    // normalize + build B operand (xn^T as bf16 hi/lo, rows = w, k = c)
    for (int i = tid; i < 8192; i += 256) {
        int c = i >> 6, w = i & 63;
        float v = (xs[i] - mu[w]) * rs[w] * norm_w[c] + norm_b[c];
        uint32_t off = ((uint32_t)(c >> 6)) * 8192u + SW128((uint32_t)(w * 128 + (c & 63) * 2));
        split_store16(smp + PRE_BH, smp + PRE_BL, off, v);
    }
    __syncthreads();

    // MMA + epilogue (bias + leaky) -> sC [w][132 pad] (aliases xs, reads done)
    {
        float c[8][4];
        conv_mma(smb, PRE_AH, PRE_AL, PRE_BH, PRE_BL, wid, lane, c);
        const int rg = lane >> 2, cg = (lane & 3) * 2;
        const int warpM = wid * 16;
        const float biaLo = conv_b[warpM + rg];
        const float biaHi = conv_b[warpM + rg + 8];
#pragma unroll
        for (int nt = 0; nt < 8; nt++) {
            const int w0c = nt * 8 + cg;
            sC[w0c * 132 + warpM + rg]           = leaky(c[nt][0] + biaLo);
            sC[(w0c + 1) * 132 + warpM + rg]     = leaky(c[nt][1] + biaLo);
            sC[w0c * 132 + warpM + rg + 8]       = leaky(c[nt][2] + biaHi);
            sC[(w0c + 1) * 132 + warpM + rg + 8] = leaky(c[nt][3] + biaHi);
        }
    }
    __syncthreads();

    // coalesced strip-split store
    const int oc0 = (tid >> 4) * 8;
    const int w0 = (tid & 15) * 4;
    float av[8][4];
#pragma unroll
    for (int j = 0; j < 4; j++) {
        float4 lo = *(const float4*)&sC[(w0 + j) * 132 + oc0];
        float4 hi = *(const float4*)&sC[(w0 + j) * 132 + oc0 + 4];
        av[0][j] = lo.x; av[1][j] = lo.y; av[2][j] = lo.z; av[3][j] = lo.w;
        av[4][j] = hi.x; av[5][j] = hi.y; av[6][j] = hi.z; av[7][j] = hi.w;
    }
    if (oc0 < 64) {
#pragma unroll
        for (int j = 0; j < 4; j++) {
            int w = w0 + j;
            float* dst = g_feat[0] + ((size_t)blockIdx.x * 64 + w) * 64 + oc0;
            *(float4*)dst = make_float4(av[0][j], av[1][j], av[2][j], av[3][j]);
            *(float4*)(dst + 4) = make_float4(av[4][j], av[5][j], av[6][j], av[7][j]);
        }
    } else {
#pragma unroll
        for (int j = 0; j < 4; j++) {
            int w = w0 + j;
            float* dst = g_feat[1] + ((size_t)(b * 64 + w) * 64 + h) * 64 + (oc0 - 64);
            *(float4*)dst = make_float4(av[0][j], av[1][j], av[2][j], av[3][j]);
            *(float4*)(dst + 4) = make_float4(av[4][j], av[5][j], av[6][j], av[7][j]);
        }
    }
}

// ============================================================================
// GCM via warp-level mma.sync bf16 3-term split. CH-TILE = 16, 2 CTAs/SM.
// (unchanged from round 10 — passing at 301 µs)
// ============================================================================
#define OFF_AHI 0u
#define OFF_ALO 8192u
#define OFF_XHI 16384u
#define OFF_XLO 32768u
#define OFF_THI 49152u
#define OFF_TLO 65536u
#define OFF_U   49152u
#define OFF_FBH 49152u
#define OFF_FBL 51200u
#define OFF_GS  57344u
#define OFF_WB  83968u
#define OFF_W2B 86080u
#define GCM_SMEM 90176u

template <bool RESID>
__device__ __forceinline__ void warp_app(uint32_t smb, char* smc, float* __restrict__ Uf,
                                         uint32_t aHiOff, uint32_t aLoOff,
                                         int wid, int lane)
{
    float c[8][4];
#pragma unroll
    for (int nt = 0; nt < 8; nt++)
#pragma unroll
        for (int j = 0; j < 4; j++) c[nt][j] = 0.f;

    const int warpM = wid * 16;
    const uint32_t aRow = warpM + (lane & 15);
    const uint32_t aK8 = (lane >> 4) * 8;
    const int q = lane >> 3;
    const uint32_t bRow = (lane & 7) + ((q >> 1) * 8);
    const uint32_t bK8 = (q & 1) * 8;

#pragma unroll
    for (int ks = 0; ks < 4; ks++) {
        const uint32_t ao = SW128(aRow * 128 + (ks * 16 + aK8) * 2);
        uint32_t aH[4], aL[4];
        ldsm4(aH, smb + aHiOff + ao);
        ldsm4(aL, smb + aLoOff + ao);
#pragma unroll
        for (int nt2 = 0; nt2 < 4; nt2++) {
            const uint32_t bo = SW128((nt2 * 16 + bRow) * 128 + (ks * 16 + bK8) * 2);
            uint32_t bH[4], bL[4];
            ldsm4(bH, smb + OFF_AHI + bo);
            ldsm4(bL, smb + OFF_ALO + bo);
            mma16816(c[nt2 * 2 + 0], aH, bH[0], bH[1]);
            mma16816(c[nt2 * 2 + 1], aH, bH[2], bH[3]);
            mma16816(c[nt2 * 2 + 0], aH, bL[0], bL[1]);
            mma16816(c[nt2 * 2 + 1], aH, bL[2], bL[3]);
            mma16816(c[nt2 * 2 + 0], aL, bH[0], bH[1]);
            mma16816(c[nt2 * 2 + 1], aL, bH[2], bH[3]);
        }
    }

    const int rg = lane >> 2, cg = (lane & 3) * 2;
    if (!RESID) {
#pragma unroll
        for (int nt = 0; nt < 8; nt++) {
            const int col = nt * 8 + cg;
            const int row0 = warpM + rg;
            *(float2*)&Uf[row0 * 68 + col] = make_float2(c[nt][0], c[nt][1]);
            *(float2*)&Uf[(row0 + 8) * 68 + col] = make_float2(c[nt][2], c[nt][3]);
        }
    } else {
#pragma unroll
        for (int nt = 0; nt < 8; nt++) {
            const int col = nt * 8 + cg;
#pragma unroll
            for (int hh = 0; hh < 2; hh++) {
                const int row = warpM + rg + hh * 8;
                const uint32_t off = SW128((uint32_t)(row * 128 + col * 2));
                __nv_bfloat162 h2 = *(__nv_bfloat162*)(smc + OFF_XHI + off);
                __nv_bfloat162 l2 = *(__nv_bfloat162*)(smc + OFF_XLO + off);
                float x0 = __bfloat162float(h2.x) + __bfloat162float(l2.x) + c[nt][hh * 2];
                float x1 = __bfloat162float(h2.y) + __bfloat162float(l2.y) + c[nt][hh * 2 + 1];
                __nv_bfloat16 nh0 = __float2bfloat16(x0);
                __nv_bfloat16 nl0 = __float2bfloat16(x0 - __bfloat162float(nh0));
                __nv_bfloat16 nh1 = __float2bfloat16(x1);
                __nv_bfloat16 nl1 = __float2bfloat16(x1 - __bfloat162float(nh1));
                __nv_bfloat162 oh; oh.x = nh0; oh.y = nh1;
                __nv_bfloat162 ol; ol.x = nl0; ol.y = nl1;
                *(__nv_bfloat162*)(smc + OFF_XHI + off) = oh;
                *(__nv_bfloat162*)(smc + OFF_XLO + off) = ol;
            }
        }
    }
}

// Small MMA: D[64 l][16 c] = adj @ B16, 3-term split. Warp w: m-tile (w&3), n-tile (w>>2).
__device__ __forceinline__ void small_mma(uint32_t smb, int wid, int lane, float ch[4])
{
    const int hwM = (wid & 3) * 16;
    const int hnt = wid >> 2;
    const uint32_t aRow = hwM + (lane & 15);
    const uint32_t aK8 = (lane >> 4) * 8;
    const int q = lane >> 3;
    const uint32_t bRow = (lane & 7) + ((q >> 1) * 8);
    const uint32_t bK8 = (q & 1) * 8;
    ch[0] = ch[1] = ch[2] = ch[3] = 0.f;
#pragma unroll
    for (int ks = 0; ks < 4; ks++) {
        uint32_t ao = SW128(aRow * 128 + (ks * 16 + aK8) * 2);
        uint32_t aH[4], aL[4];
        ldsm4(aH, smb + OFF_AHI + ao);
        ldsm4(aL, smb + OFF_ALO + ao);
        uint32_t bo = SW128(bRow * 128 + (ks * 16 + bK8) * 2);
        uint32_t bH[4], bL[4];
        ldsm4(bH, smb + OFF_FBH + bo);
        ldsm4(bL, smb + OFF_FBL + bo);
        uint32_t b0H = hnt ? bH[2] : bH[0], b1H = hnt ? bH[3] : bH[1];
        uint32_t b0L = hnt ? bL[2] : bL[0], b1L = hnt ? bL[3] : bL[1];
        mma16816(ch, aH, b0H, b1H);
        mma16816(ch, aH, b0L, b1L);
        mma16816(ch, aL, b0H, b1H);
    }
}

__device__ __forceinline__ void store_row_split32(char* smc, uint32_t hiOff, uint32_t loOff,
                                                  int r, int cb, const float* v) {
    const uint32_t rowb = (uint32_t)r * 128;
#pragma unroll
    for (int j = 0; j < 32; j += 8) {
        ushort hi[8], lo[8];
#pragma unroll
        for (int qq = 0; qq < 8; qq++) {
            float x = v[j + qq];
            __nv_bfloat16 h = __float2bfloat16(x);
            __nv_bfloat16 l = __float2bfloat16(x - __bfloat162float(h));
            hi[qq] = *(ushort*)&h; lo[qq] = *(ushort*)&l;
        }
        uint32_t o = SW128(rowb + (cb + j) * 2);
        *(uint4*)(smc + hiOff + o) = *(uint4*)hi;
        *(uint4*)(smc + loOff + o) = *(uint4*)lo;
    }
}

__global__ __launch_bounds__(256, 2) void k_gcm(
    const float* __restrict__ adj_h, const float* __restrict__ adj_v,
    const float* __restrict__ head_h, const float* __restrict__ tail_h,
    const float* __restrict__ w1_h, const float* __restrict__ w2_h,
    const float* __restrict__ head_v, const float* __restrict__ tail_v,
    const float* __restrict__ w1_v, const float* __restrict__ w2_v)
{
    extern __shared__ __align__(1024) char sm[];
    const uint32_t smb = smem_u32(sm);
    float* Uf = (float*)(sm + OFF_U);
    float* WB = (float*)(sm + OFF_WB);
    float* gS = (float*)(sm + OFF_GS);
    const int tid = threadIdx.x;
    const int wid = tid >> 5, lane = tid & 31;
    const int graph = blockIdx.x, ct = blockIdx.y, dir = blockIdx.z;
    const float* adj = dir ? adj_v : adj_h;
    const float* hw = dir ? head_v : head_h;
    const float* tw = dir ? tail_v : tail_h;
    const float* w1 = dir ? w1_v : w1_h;
    const float* w2 = dir ? w2_v : w2_h;
    const float* feat = g_feat[dir] + (size_t)graph * 4096 + ct * 16;
    float* gout = g_gout[dir] + (size_t)graph * 4096 + ct * 16;

    for (int i = tid; i < 4096; i += 256) {
        int l = i >> 6, m = i & 63;
        float v = adj[i];
        __nv_bfloat16 h = __float2bfloat16(v);
        __nv_bfloat16 lo = __float2bfloat16(v - __bfloat162float(h));
        uint32_t o = SW128((uint32_t)(l * 128 + m * 2));
        *(__nv_bfloat16*)(sm + OFF_AHI + o) = h;
        *(__nv_bfloat16*)(sm + OFF_ALO + o) = lo;
    }
    for (int i = tid; i < 1024; i += 256) {
        int m = i >> 4, c = i & 15;
        float v = feat[m * 64 + c];
        __nv_bfloat16 h = __float2bfloat16(v);
        __nv_bfloat16 lo = __float2bfloat16(v - __bfloat162float(h));
        uint32_t o = SW128((uint32_t)(c * 128 + m * 2));
        *(__nv_bfloat16*)(sm + OFF_FBH + o) = h;
        *(__nv_bfloat16*)(sm + OFF_FBL + o) = lo;
    }
    for (int i = tid; i < 528; i += 256) {
        float v;
        if (i < 8) v = hw[i];
        else if (i < 16) v = tw[i - 8];
        else if (i < 272) v = w1[i - 16];
        else v = w2[i - 272];
        WB[i] = v;
    }
    for (int i = tid; i < 512; i += 256) {
        int it = i >> 7, rest = i & 127;
        int s = rest >> 6, idx = rest & 63;
        float v = s ? w2[it * 64 + idx] : w1[it * 64 + idx];
        *(float2*)(sm + OFF_W2B + (size_t)i * 8) = make_float2(v, v);
    }
    __syncthreads();

    // head
    {
        float ch[4];
        small_mma(smb, wid, lane, ch);
        const int rg = lane >> 2, cg = (lane & 3) * 2;
        const int col = (wid >> 2) * 8 + cg;
        const int row = (wid & 3) * 16 + rg;
        *(float2*)&gS[row * 18 + col] = make_float2(ch[0], ch[1]);
        *(float2*)&gS[(row + 8) * 18 + col] = make_float2(ch[2], ch[3]);
    }
    __syncthreads();

    {
        const int r = tid >> 1, half = tid & 1;
        const int c = r >> 3, f = r & 7;
        const float hf = WB[f];
        const int cb = half * 32;
        float v[32];
#pragma unroll
        for (int l = 0; l < 32; l++) v[l] = gS[(cb + l) * 18 + c] * hf;
        store_row_split32(sm, OFF_XHI, OFF_XLO, r, cb, v);
    }
    __syncthreads();

    const int nn = tid & 63;
    const int c0 = tid >> 6;

    for (int it = 0; it < 4; it++) {
        warp_app<false>(smb, sm, Uf, OFF_XHI, OFF_XLO, wid, lane);
        __syncthreads();
        {
            float vi[4][8];
#pragma unroll
            for (int p = 0; p < 4; p++) {
                int cc = c0 + p * 4;
#pragma unroll
                for (int f = 0; f < 8; f++) vi[p][f] = Uf[(cc * 8 + f) * 68 + nn];
            }
            __syncthreads();

            uint64_t V[2][8];
#pragma unroll
            for (int qq = 0; qq < 2; qq++)
#pragma unroll
                for (int f = 0; f < 8; f++) V[qq][f] = pk2(vi[2 * qq][f], vi[2 * qq + 1][f]);

            const char* wbase = sm + OFF_W2B + it * 1024;
            uint64_t m2[2][8];
#pragma unroll
            for (int qq = 0; qq < 2; qq++)
#pragma unroll
                for (int f = 0; f < 8; f++) m2[qq][f] = 0ull;
#pragma unroll
            for (int fi = 0; fi < 8; fi++) {
                const char* wr = wbase + fi * 64;
                ulonglong2 wa = *(const ulonglong2*)(wr);
                ulonglong2 wb = *(const ulonglong2*)(wr + 16);
                ulonglong2 wc = *(const ulonglong2*)(wr + 32);
                ulonglong2 wd = *(const ulonglong2*)(wr + 48);
#pragma unroll
                for (int qq = 0; qq < 2; qq++) {
                    m2[qq][0] = fma2(V[qq][fi], wa.x, m2[qq][0]);
                    m2[qq][1] = fma2(V[qq][fi], wa.y, m2[qq][1]);
                    m2[qq][2] = fma2(V[qq][fi], wb.x, m2[qq][2]);
                    m2[qq][3] = fma2(V[qq][fi], wb.y, m2[qq][3]);
                    m2[qq][4] = fma2(V[qq][fi], wc.x, m2[qq][4]);
                    m2[qq][5] = fma2(V[qq][fi], wc.y, m2[qq][5]);
                    m2[qq][6] = fma2(V[qq][fi], wd.x, m2[qq][6]);
                    m2[qq][7] = fma2(V[qq][fi], wd.y, m2[qq][7]);
                }
            }
#pragma unroll
            for (int qq = 0; qq < 2; qq++)
#pragma unroll
                for (int f = 0; f < 8; f++) {
                    float a, b2;
                    upk2(m2[qq][f], a, b2);
                    m2[qq][f] = pk2(leaky(a), leaky(b2));
                }
            const char* wbase2 = wbase + 512;
            uint64_t o2[2][8];
#pragma unroll
            for (int qq = 0; qq < 2; qq++)
#pragma unroll
                for (int f = 0; f < 8; f++) o2[qq][f] = 0ull;
#pragma unroll
            for (int fi = 0; fi < 8; fi++) {
                const char* wr = wbase2 + fi * 64;
                ulonglong2 wa = *(const ulonglong2*)(wr);
                ulonglong2 wb = *(const ulonglong2*)(wr + 16);
                ulonglong2 wc = *(const ulonglong2*)(wr + 32);
                ulonglong2 wd = *(const ulonglong2*)(wr + 48);
#pragma unroll
                for (int qq = 0; qq < 2; qq++) {
                    o2[qq][0] = fma2(m2[qq][fi], wa.x, o2[qq][0]);
                    o2[qq][1] = fma2(m2[qq][fi], wa.y, o2[qq][1]);
                    o2[qq][2] = fma2(m2[qq][fi], wb.x, o2[qq][2]);
                    o2[qq][3] = fma2(m2[qq][fi], wb.y, o2[qq][3]);
                    o2[qq][4] = fma2(m2[qq][fi], wc.x, o2[qq][4]);
                    o2[qq][5] = fma2(m2[qq][fi], wc.y, o2[qq][5]);
                    o2[qq][6] = fma2(m2[qq][fi], wd.x, o2[qq][6]);
                    o2[qq][7] = fma2(m2[qq][fi], wd.y, o2[qq][7]);
                }
            }
#pragma unroll
            for (int qq = 0; qq < 2; qq++) {
                const int ca = c0 + (2 * qq) * 4;
                const int cb2 = c0 + (2 * qq + 1) * 4;
#pragma unroll
                for (int f = 0; f < 8; f++) {
                    float x0, x1;
                    upk2(o2[qq][f], x0, x1);
                    uint32_t oA = SW128((uint32_t)((ca * 8 + f) * 128 + nn * 2));
                    split_store16(sm + OFF_THI, sm + OFF_TLO, oA, x0);
                    uint32_t oB = SW128((uint32_t)((cb2 * 8 + f) * 128 + nn * 2));
                    split_store16(sm + OFF_THI, sm + OFF_TLO, oB, x1);
                }
            }
        }
        __syncthreads();

        warp_app<true>(smb, sm, Uf, OFF_THI, OFF_TLO, wid, lane);
        __syncwarp();
        __syncthreads();
    }

    // tail
#pragma unroll
    for (int p = 0; p < 4; p++) {
        int idx = tid + p * 256;
        int m = idx & 63, c = idx >> 6;
        float s = 0.f;
#pragma unroll
        for (int f = 0; f < 8; f++) {
            uint32_t off = SW128((uint32_t)((c * 8 + f) * 128 + m * 2));
            float xv = __bfloat162float(*(__nv_bfloat16*)(sm + OFF_XHI + off))
                     + __bfloat162float(*(__nv_bfloat16*)(sm + OFF_XLO + off));
            s = fmaf(xv, WB[8 + f], s);
        }
        uint32_t o = SW128((uint32_t)(c * 128 + m * 2));
        split_store16(sm + OFF_FBH, sm + OFF_FBL, o, s);
    }
    __syncthreads();

    {
        float ch[4];
        small_mma(smb, wid, lane, ch);
        const int rg = lane >> 2, cg = (lane & 3) * 2;
        const int col = (wid >> 2) * 8 + cg;
        const int row = (wid & 3) * 16 + rg;
        *(float2*)&gout[row * 64 + col] = make_float2(leaky(ch[0]), leaky(ch[1]));
        *(float2*)&gout[(row + 8) * 64 + col] = make_float2(leaky(ch[2]), leaky(ch[3]));
    }
}

// ============================================================================
// Kernel 3: gather + fuse 1x1 conv (MMA) + bias + residual
// Smem: SC(fp32 [64][132]) 0..33792, AH 34816(32K), AL 67584, BH 100352(16K), BL 116736
// ============================================================================
#define FU_SC 0u
#define FU_AH 34816u
#define FU_AL 67584u
#define FU_BH 100352u
#define FU_BL 116736u
#define FU_SMEM 133120u

__global__ __launch_bounds__(256) void k_fuse(
    const float* __restrict__ x, const float* __restrict__ fuse_w,
    const float* __restrict__ fuse_b, float* __restrict__ out)
{
    extern __shared__ __align__(1024) char smf[];
    const uint32_t smb = smem_u32(smf);
    float* sC = (float*)(smf + FU_SC);
    const int tid = threadIdx.x;
    const int wid = tid >> 5, lane = tid & 31;
    const int b = blockIdx.x >> 6, h = blockIdx.x & 63;

    // B operand: attn^T (rows = w, k = c), bf16 hi/lo, 2 K-tiles
    const float* gh = g_gout[0] + (size_t)blockIdx.x * 4096;  // [w][c] for c<64
    for (int i = tid; i < 4096; i += 256) {
        int w = i >> 6, c = i & 63;
        uint32_t off = SW128((uint32_t)(w * 128 + c * 2));
        split_store16(smf + FU_BH, smf + FU_BL, off, gh[i]);
    }
    const float* gvbase = g_gout[1] + (size_t)b * 64 * 4096 + h * 64;  // [w][c] for c>=64
    for (int i = tid; i < 4096; i += 256) {
        int w = i >> 6, c = i & 63;
        uint32_t off = 8192u + SW128((uint32_t)(w * 128 + c * 2));
        split_store16(smf + FU_BH, smf + FU_BL, off, gvbase[(size_t)w * 4096 + c]);
    }
    // A operand: fuse_w
    for (int i = tid; i < 16384; i += 256) {
        int oc = i >> 7, cc = i & 127;
        uint32_t off = ((uint32_t)(cc >> 6)) * 16384u + SW128((uint32_t)(oc * 128 + (cc & 63) * 2));
        split_store16(smf + FU_AH, smf + FU_AL, off, fuse_w[i]);
    }
    __syncthreads();

    // MMA -> sC (raw)
    {
        float c[8][4];
        conv_mma(smb, FU_AH, FU_AL, FU_BH, FU_BL, wid, lane, c);
        const int rg = lane >> 2, cg = (lane & 3) * 2;
        const int warpM = wid * 16;
#pragma unroll
        for (int nt = 0; nt < 8; nt++) {
            const int w0c = nt * 8 + cg;
            sC[w0c * 132 + warpM + rg]           = c[nt][0];
            sC[(w0c + 1) * 132 + warpM + rg]     = c[nt][1];
            sC[w0c * 132 + warpM + rg + 8]       = c[nt][2];
            sC[(w0c + 1) * 132 + warpM + rg + 8] = c[nt][3];
        }
    }
    __syncthreads();

    // bias + residual + store
    const int oc0 = (tid >> 4) * 8;
    const int w0 = (tid & 15) * 4;
    float av[8][4];
#pragma unroll
    for (int j = 0; j < 4; j++) {
        float4 lo = *(const float4*)&sC[(w0 + j) * 132 + oc0];
        float4 hi = *(const float4*)&sC[(w0 + j) * 132 + oc0 + 4];
        av[0][j] = lo.x; av[1][j] = lo.y; av[2][j] = lo.z; av[3][j] = lo.w;
        av[4][j] = hi.x; av[5][j] = hi.y; av[6][j] = hi.z; av[7][j] = hi.w;
    }
    const float* xblk = x + (size_t)b * 128 * 4096 + h * 64;
    float* oblk = out + (size_t)b * 128 * 4096 + h * 64;
#pragma unroll
    for (int i = 0; i < 8; i++) {
        int oc = oc0 + i;
        float bia = fuse_b[oc];
        float4 xv = *(const float4*)(xblk + (size_t)oc * 4096 + w0);
        *(float4*)(oblk + (size_t)oc * 4096 + w0) =
            make_float4(av[i][0] + bia + xv.x, av[i][1] + bia + xv.y,
                        av[i][2] + bia + xv.z, av[i][3] + bia + xv.w);
    }
}

extern "C" void kernel_launch(void* const* d_in, const int* in_sizes, int n_in,
                              void* d_out, int out_size)
{
    const float* x      = (const float*)d_in[0];
    const float* adj_h  = (const float*)d_in[1];
    const float* adj_v  = (const float*)d_in[2];
    const float* norm_w = (const float*)d_in[3];
    const float* norm_b = (const float*)d_in[4];
    const float* conv_w = (const float*)d_in[5];
    const float* conv_b = (const float*)d_in[6];
    const float* fuse_w = (const float*)d_in[7];
    const float* fuse_b = (const float*)d_in[8];
    const float* head_h = (const float*)d_in[9];
    const float* tail_h = (const float*)d_in[10];
    const float* w1_h   = (const float*)d_in[11];
    const float* w2_h   = (const float*)d_in[12];
    const float* head_v = (const float*)d_in[13];
    const float* tail_v = (const float*)d_in[14];
    const float* w1_v   = (const float*)d_in[15];
    const float* w2_v   = (const float*)d_in[16];
    float* out = (float*)d_out;

    cudaFuncSetAttribute(k_pre, cudaFuncAttributeMaxDynamicSharedMemorySize, (int)PRE_SMEM);
    cudaFuncSetAttribute(k_gcm, cudaFuncAttributeMaxDynamicSharedMemorySize, (int)GCM_SMEM);
    cudaFuncSetAttribute(k_fuse, cudaFuncAttributeMaxDynamicSharedMemorySize, (int)FU_SMEM);

    k_pre<<<256, 256, PRE_SMEM>>>(x, norm_w, norm_b, conv_w, conv_b);
    k_gcm<<<dim3(256, 4, 2), 256, GCM_SMEM>>>(adj_h, adj_v, head_h, tail_h, w1_h, w2_h,
                                              head_v, tail_v, w1_v, w2_v);
    k_fuse<<<256, 256, FU_SMEM>>>(x, fuse_w, fuse_b, out);
}

// round 13
// speedup vs baseline: 1.0607x; 1.0607x over previous
#include <cuda_runtime.h>
#include <cuda_bf16.h>
#include <cstdint>

#define LRELU_SLOPE 0.2f

// Scratch: [dir][graph(256)][node(64)][ch(64)]
__device__ float g_feat[2][256 * 64 * 64];
__device__ float g_gout[2][256 * 64 * 64];

__device__ __forceinline__ float leaky(float v) { return v >= 0.f ? v : LRELU_SLOPE * v; }

// ---- packed f32x2 helpers ----
__device__ __forceinline__ uint64_t pk2(float x, float y) {
    uint64_t r; asm("mov.b64 %0, {%1, %2};" : "=l"(r) : "f"(x), "f"(y)); return r;
}
__device__ __forceinline__ void upk2(uint64_t v, float& x, float& y) {
    asm("mov.b64 {%0, %1}, %2;" : "=f"(x), "=f"(y) : "l"(v));
}
__device__ __forceinline__ uint64_t fma2(uint64_t a, uint64_t b, uint64_t c) {
    uint64_t d; asm("fma.rn.f32x2 %0, %1, %2, %3;" : "=l"(d) : "l"(a), "l"(b), "l"(c)); return d;
}

__device__ __forceinline__ uint32_t smem_u32(const void* p) {
    uint32_t a;
    asm("{ .reg .u64 t; cvta.to.shared.u64 t, %1; cvt.u32.u64 %0, t; }" : "=r"(a) : "l"(p));
    return a;
}
#define SW128(o) ((o) ^ (((o) >> 3) & 0x70))

__device__ __forceinline__ void ldsm4(uint32_t r[4], uint32_t addr) {
    asm volatile("ldmatrix.sync.aligned.m8n8.x4.shared.b16 {%0,%1,%2,%3}, [%4];"
                 : "=r"(r[0]), "=r"(r[1]), "=r"(r[2]), "=r"(r[3]) : "r"(addr));
}
__device__ __forceinline__ void mma16816(float c[4], const uint32_t a[4], uint32_t b0, uint32_t b1) {
    asm volatile(
        "mma.sync.aligned.m16n8k16.row.col.f32.bf16.bf16.f32 "
        "{%0,%1,%2,%3}, {%4,%5,%6,%7}, {%8,%9}, {%0,%1,%2,%3};"
        : "+f"(c[0]), "+f"(c[1]), "+f"(c[2]), "+f"(c[3])
        : "r"(a[0]), "r"(a[1]), "r"(a[2]), "r"(a[3]), "r"(b0), "r"(b1));
}

// ============================================================================
// Kernel 1: LayerNorm + 1x1 conv + leaky + strip split (FFMA2 GEMM loop)
// ============================================================================
__global__ __launch_bounds__(256) void k_pre(
    const float* __restrict__ x, const float* __restrict__ norm_w,
    const float* __restrict__ norm_b, const float* __restrict__ conv_w,
    const float* __restrict__ conv_b)
{
    extern __shared__ float sm_pre[];
    float* xs = sm_pre;
    float* ws = sm_pre + 128 * 64;
    float* mu = ws + 128 * 132;
    float* rs = mu + 64;
    const int tid = threadIdx.x;
    const int b = blockIdx.x >> 6, h = blockIdx.x & 63;
    const float* xblk = x + (size_t)b * 128 * 4096 + h * 64;

    for (int i = tid; i < 128 * 64; i += 256) {
        int c = i >> 6, w = i & 63;
        xs[i] = xblk[c * 4096 + w];
    }
    for (int i = tid; i < 128 * 128; i += 256) {
        int oc = i >> 7, c = i & 127;
        ws[c * 132 + oc] = conv_w[i];
    }
    __syncthreads();
    if (tid < 64) {
        float s = 0.f, s2 = 0.f;
#pragma unroll 8
        for (int c = 0; c < 128; c++) { float v = xs[c * 64 + tid]; s += v; s2 += v * v; }
        float m = s * 0.0078125f;
        float var = s2 * 0.0078125f - m * m;
        mu[tid] = m; rs[tid] = rsqrtf(var + 1e-5f);
    }
    __syncthreads();
    for (int i = tid; i < 128 * 64; i += 256) {
        int c = i >> 6, w = i & 63;
        xs[i] = (xs[i] - mu[w]) * rs[w] * norm_w[c] + norm_b[c];
    }
    __syncthreads();

    const int oc0 = (tid >> 4) * 8;
    const int w0 = (tid & 15) * 4;
    uint64_t acc2[16];
#pragma unroll
    for (int i = 0; i < 16; i++) acc2[i] = 0ull;
#pragma unroll 4
    for (int c = 0; c < 128; c++) {
        float4 a0 = *(const float4*)(ws + c * 132 + oc0);
        float4 a1 = *(const float4*)(ws + c * 132 + oc0 + 4);
        ulonglong2 bv = *(const ulonglong2*)(xs + c * 64 + w0);
        uint64_t d;
        d = pk2(a0.x, a0.x); acc2[0]  = fma2(d, bv.x, acc2[0]);  acc2[1]  = fma2(d, bv.y, acc2[1]);
        d = pk2(a0.y, a0.y); acc2[2]  = fma2(d, bv.x, acc2[2]);  acc2[3]  = fma2(d, bv.y, acc2[3]);
        d = pk2(a0.z, a0.z); acc2[4]  = fma2(d, bv.x, acc2[4]);  acc2[5]  = fma2(d, bv.y, acc2[5]);
        d = pk2(a0.w, a0.w); acc2[6]  = fma2(d, bv.x, acc2[6]);  acc2[7]  = fma2(d, bv.y, acc2[7]);
        d = pk2(a1.x, a1.x); acc2[8]  = fma2(d, bv.x, acc2[8]);  acc2[9]  = fma2(d, bv.y, acc2[9]);
        d = pk2(a1.y, a1.y); acc2[10] = fma2(d, bv.x, acc2[10]); acc2[11] = fma2(d, bv.y, acc2[11]);
        d = pk2(a1.z, a1.z); acc2[12] = fma2(d, bv.x, acc2[12]); acc2[13] = fma2(d, bv.y, acc2[13]);
        d = pk2(a1.w, a1.w); acc2[14] = fma2(d, bv.x, acc2[14]); acc2[15] = fma2(d, bv.y, acc2[15]);
    }
    float av[8][4];
#pragma unroll
    for (int i = 0; i < 8; i++) {
        upk2(acc2[2 * i], av[i][0], av[i][1]);
        upk2(acc2[2 * i + 1], av[i][2], av[i][3]);
        float bia = conv_b[oc0 + i];
#pragma unroll
        for (int j = 0; j < 4; j++) av[i][j] = leaky(av[i][j] + bia);
    }
    if (oc0 < 64) {
#pragma unroll
        for (int j = 0; j < 4; j++) {
            int w = w0 + j;
            float* dst = g_feat[0] + ((size_t)blockIdx.x * 64 + w) * 64 + oc0;
            *(float4*)dst = make_float4(av[0][j], av[1][j], av[2][j], av[3][j]);
            *(float4*)(dst + 4) = make_float4(av[4][j], av[5][j], av[6][j], av[7][j]);
        }
    } else {
#pragma unroll
        for (int j = 0; j < 4; j++) {
            int w = w0 + j;
            float* dst = g_feat[1] + ((size_t)(b * 64 + w) * 64 + h) * 64 + (oc0 - 64);
            *(float4*)dst = make_float4(av[0][j], av[1][j], av[2][j], av[3][j]);
            *(float4*)(dst + 4) = make_float4(av[4][j], av[5][j], av[6][j], av[7][j]);
        }
    }
}

// ============================================================================
// GCM via warp-level mma.sync bf16 3-term split. CH-TILE = 16, 2 CTAs/SM.
// Head and tail adj-GEMMs also on MMA (B = 16-row operand in T region).
// ============================================================================
#define OFF_AHI 0u
#define OFF_ALO 8192u
#define OFF_XHI 16384u
#define OFF_XLO 32768u
#define OFF_THI 49152u
#define OFF_TLO 65536u
#define OFF_U   49152u
#define OFF_FBH 49152u            // 16-row B operand hi (head: feat^T, tail: t^T)
#define OFF_FBL 51200u            // 16-row B operand lo
#define OFF_GS  57344u            // gS fp32 [64][18] (head output)
#define OFF_WB  83968u
#define OFF_W2B 86080u
#define GCM_SMEM 90176u

template <bool RESID>
__device__ __forceinline__ void warp_app(uint32_t smb, char* smc, float* __restrict__ Uf,
                                         uint32_t aHiOff, uint32_t aLoOff,
                                         int wid, int lane)
{
    float c[8][4];
#pragma unroll
    for (int nt = 0; nt < 8; nt++)
#pragma unroll
        for (int j = 0; j < 4; j++) c[nt][j] = 0.f;

    const int warpM = wid * 16;
    const uint32_t aRow = warpM + (lane & 15);
    const uint32_t aK8 = (lane >> 4) * 8;
    const int q = lane >> 3;
    const uint32_t bRow = (lane & 7) + ((q >> 1) * 8);
    const uint32_t bK8 = (q & 1) * 8;

#pragma unroll
    for (int ks = 0; ks < 4; ks++) {
        const uint32_t ao = SW128(aRow * 128 + (ks * 16 + aK8) * 2);
        uint32_t aH[4], aL[4];
        ldsm4(aH, smb + aHiOff + ao);
        ldsm4(aL, smb + aLoOff + ao);
#pragma unroll
        for (int nt2 = 0; nt2 < 4; nt2++) {
            const uint32_t bo = SW128((nt2 * 16 + bRow) * 128 + (ks * 16 + bK8) * 2);
            uint32_t bH[4], bL[4];
            ldsm4(bH, smb + OFF_AHI + bo);
            ldsm4(bL, smb + OFF_ALO + bo);
            mma16816(c[nt2 * 2 + 0], aH, bH[0], bH[1]);
            mma16816(c[nt2 * 2 + 1], aH, bH[2], bH[3]);
            mma16816(c[nt2 * 2 + 0], aH, bL[0], bL[1]);
            mma16816(c[nt2 * 2 + 1], aH, bL[2], bL[3]);
            mma16816(c[nt2 * 2 + 0], aL, bH[0], bH[1]);
            mma16816(c[nt2 * 2 + 1], aL, bH[2], bH[3]);
        }
    }

    const int rg = lane >> 2, cg = (lane & 3) * 2;
    if (!RESID) {
#pragma unroll
        for (int nt = 0; nt < 8; nt++) {
            const int col = nt * 8 + cg;
            const int row0 = warpM + rg;
            *(float2*)&Uf[row0 * 68 + col] = make_float2(c[nt][0], c[nt][1]);
            *(float2*)&Uf[(row0 + 8) * 68 + col] = make_float2(c[nt][2], c[nt][3]);
        }
    } else {
#pragma unroll
        for (int nt = 0; nt < 8; nt++) {
            const int col = nt * 8 + cg;
#pragma unroll
            for (int hh = 0; hh < 2; hh++) {
                const int row = warpM + rg + hh * 8;
                const uint32_t off = SW128((uint32_t)(row * 128 + col * 2));
                __nv_bfloat162 h2 = *(__nv_bfloat162*)(smc + OFF_XHI + off);
                __nv_bfloat162 l2 = *(__nv_bfloat162*)(smc + OFF_XLO + off);
                float x0 = __bfloat162float(h2.x) + __bfloat162float(l2.x) + c[nt][hh * 2];
                float x1 = __bfloat162float(h2.y) + __bfloat162float(l2.y) + c[nt][hh * 2 + 1];
                __nv_bfloat16 nh0 = __float2bfloat16(x0);
                __nv_bfloat16 nl0 = __float2bfloat16(x0 - __bfloat162float(nh0));
                __nv_bfloat16 nh1 = __float2bfloat16(x1);
                __nv_bfloat16 nl1 = __float2bfloat16(x1 - __bfloat162float(nh1));
                __nv_bfloat162 oh; oh.x = nh0; oh.y = nh1;
                __nv_bfloat162 ol; ol.x = nl0; ol.y = nl1;
                *(__nv_bfloat162*)(smc + OFF_XHI + off) = oh;
                *(__nv_bfloat162*)(smc + OFF_XLO + off) = ol;
            }
        }
    }
}

// Small MMA: D[64 l][16 c] = adj @ B16, 3-term split. Warp w: m-tile (w&3), n-tile (w>>2).
__device__ __forceinline__ void small_mma(uint32_t smb, int wid, int lane, float ch[4])
{
    const int hwM = (wid & 3) * 16;
    const int hnt = wid >> 2;
    const uint32_t aRow = hwM + (lane & 15);
    const uint32_t aK8 = (lane >> 4) * 8;
    const int q = lane >> 3;
    const uint32_t bRow = (lane & 7) + ((q >> 1) * 8);
    const uint32_t bK8 = (q & 1) * 8;
    ch[0] = ch[1] = ch[2] = ch[3] = 0.f;
#pragma unroll
    for (int ks = 0; ks < 4; ks++) {
        uint32_t ao = SW128(aRow * 128 + (ks * 16 + aK8) * 2);
        uint32_t aH[4], aL[4];
        ldsm4(aH, smb + OFF_AHI + ao);
        ldsm4(aL, smb + OFF_ALO + ao);
        uint32_t bo = SW128(bRow * 128 + (ks * 16 + bK8) * 2);
        uint32_t bH[4], bL[4];
        ldsm4(bH, smb + OFF_FBH + bo);
        ldsm4(bL, smb + OFF_FBL + bo);
        uint32_t b0H = hnt ? bH[2] : bH[0], b1H = hnt ? bH[3] : bH[1];
        uint32_t b0L = hnt ? bL[2] : bL[0], b1L = hnt ? bL[3] : bL[1];
        mma16816(ch, aH, b0H, b1H);
        mma16816(ch, aH, b0L, b1L);
        mma16816(ch, aL, b0H, b1H);
    }
}

__device__ __forceinline__ void store_row_split32(char* smc, uint32_t hiOff, uint32_t loOff,
                                                  int r, int cb, const float* v) {
    const uint32_t rowb = (uint32_t)r * 128;
#pragma unroll
    for (int j = 0; j < 32; j += 8) {
        ushort hi[8], lo[8];
#pragma unroll
        for (int qq = 0; qq < 8; qq++) {
            float x = v[j + qq];
            __nv_bfloat16 h = __float2bfloat16(x);
            __nv_bfloat16 l = __float2bfloat16(x - __bfloat162float(h));
            hi[qq] = *(ushort*)&h; lo[qq] = *(ushort*)&l;
        }
        uint32_t o = SW128(rowb + (cb + j) * 2);
        *(uint4*)(smc + hiOff + o) = *(uint4*)hi;
        *(uint4*)(smc + loOff + o) = *(uint4*)lo;
    }
}

__global__ __launch_bounds__(256, 2) void k_gcm(
    const float* __restrict__ adj_h, const float* __restrict__ adj_v,
    const float* __restrict__ head_h, const float* __restrict__ tail_h,
    const float* __restrict__ w1_h, const float* __restrict__ w2_h,
    const float* __restrict__ head_v, const float* __restrict__ tail_v,
    const float* __restrict__ w1_v, const float* __restrict__ w2_v)
{
    extern __shared__ __align__(1024) char sm[];
    const uint32_t smb = smem_u32(sm);
    float* Uf = (float*)(sm + OFF_U);
    float* WB = (float*)(sm + OFF_WB);
    float* gS = (float*)(sm + OFF_GS);
    const int tid = threadIdx.x;
    const int wid = tid >> 5, lane = tid & 31;
    const int graph = blockIdx.x, ct = blockIdx.y, dir = blockIdx.z;
    const float* adj = dir ? adj_v : adj_h;
    const float* hw = dir ? head_v : head_h;
    const float* tw = dir ? tail_v : tail_h;
    const float* w1 = dir ? w1_v : w1_h;
    const float* w2 = dir ? w2_v : w2_h;
    const float* feat = g_feat[dir] + (size_t)graph * 4096 + ct * 16;
    float* gout = g_gout[dir] + (size_t)graph * 4096 + ct * 16;

    // ---- stage adj bf16 hi/lo (vectorized: 8 contiguous m per item) ----
    for (int i = tid; i < 512; i += 256) {
        const int l = i >> 3, mb = (i & 7) * 8;
        float4 v0 = *(const float4*)(adj + l * 64 + mb);
        float4 v1 = *(const float4*)(adj + l * 64 + mb + 4);
        float vv[8] = {v0.x, v0.y, v0.z, v0.w, v1.x, v1.y, v1.z, v1.w};
        ushort hi[8], lo[8];
#pragma unroll
        for (int qq = 0; qq < 8; qq++) {
            __nv_bfloat16 h = __float2bfloat16(vv[qq]);
            __nv_bfloat16 ll = __float2bfloat16(vv[qq] - __bfloat162float(h));
            hi[qq] = *(ushort*)&h; lo[qq] = *(ushort*)&ll;
        }
        uint32_t o = SW128((uint32_t)(l * 128 + mb * 2));
        *(uint4*)(sm + OFF_AHI + o) = *(uint4*)hi;
        *(uint4*)(sm + OFF_ALO + o) = *(uint4*)lo;
    }
    for (int i = tid; i < 1024; i += 256) {
        int m = i >> 4, c = i & 15;
        float v = feat[m * 64 + c];
        __nv_bfloat16 h = __float2bfloat16(v);
        __nv_bfloat16 lo = __float2bfloat16(v - __bfloat162float(h));
        uint32_t o = SW128((uint32_t)(c * 128 + m * 2));
        *(__nv_bfloat16*)(sm + OFF_FBH + o) = h;
        *(__nv_bfloat16*)(sm + OFF_FBL + o) = lo;
    }
    for (int i = tid; i < 528; i += 256) {
        float v;
        if (i < 8) v = hw[i];
        else if (i < 16) v = tw[i - 8];
        else if (i < 272) v = w1[i - 16];
        else v = w2[i - 272];
        WB[i] = v;
    }
    for (int i = tid; i < 512; i += 256) {
        int it = i >> 7, rest = i & 127;
        int s = rest >> 6, idx = rest & 63;
        float v = s ? w2[it * 64 + idx] : w1[it * 64 + idx];
        *(float2*)(sm + OFF_W2B + (size_t)i * 8) = make_float2(v, v);
    }
    __syncthreads();

    // ---- head: g = adj @ feat via small MMA ----
    {
        float ch[4];
        small_mma(smb, wid, lane, ch);
        const int rg = lane >> 2, cg = (lane & 3) * 2;
        const int col = (wid >> 2) * 8 + cg;
        const int row = (wid & 3) * 16 + rg;
        *(float2*)&gS[row * 18 + col] = make_float2(ch[0], ch[1]);
        *(float2*)&gS[(row + 8) * 18 + col] = make_float2(ch[2], ch[3]);
    }
    __syncthreads();

    // X[r][l] = g[l][c] * hw[f]  -> XHI/XLO
    {
        const int r = tid >> 1, half = tid & 1;
        const int c = r >> 3, f = r & 7;
        const float hf = WB[f];
        const int cb = half * 32;
        float v[32];
#pragma unroll
        for (int l = 0; l < 32; l++) v[l] = gS[(cb + l) * 18 + c] * hf;
        store_row_split32(sm, OFF_XHI, OFF_XLO, r, cb, v);
    }
    __syncthreads();

    const int nn = tid & 63;
    const int c0 = tid >> 6;  // cc[p] = c0 + p*4

    // ---- ResGCN body ----
    for (int it = 0; it < 4; it++) {
        warp_app<false>(smb, sm, Uf, OFF_XHI, OFF_XLO, wid, lane);
        __syncthreads();

        // fmix: T = leaky(U W1) W2 -> THI/TLO (packed f32x2)
        {
            float vi[4][8];
#pragma unroll
            for (int p = 0; p < 4; p++) {
                int cc = c0 + p * 4;
#pragma unroll
                for (int f = 0; f < 8; f++) vi[p][f] = Uf[(cc * 8 + f) * 68 + nn];
            }
            __syncthreads();  // Uf reads done before T writes (alias)

            uint64_t V[2][8];
#pragma unroll
            for (int qq = 0; qq < 2; qq++)
#pragma unroll
                for (int f = 0; f < 8; f++) V[qq][f] = pk2(vi[2 * qq][f], vi[2 * qq + 1][f]);

            const char* wbase = sm + OFF_W2B + it * 1024;
            uint64_t m2[2][8];
#pragma unroll
            for (int qq = 0; qq < 2; qq++)
#pragma unroll
                for (int f = 0; f < 8; f++) m2[qq][f] = 0ull;
#pragma unroll
            for (int fi = 0; fi < 8; fi++) {
                const char* wr = wbase + fi * 64;
                ulonglong2 wa = *(const ulonglong2*)(wr);
                ulonglong2 wb = *(const ulonglong2*)(wr + 16);
                ulonglong2 wc = *(const ulonglong2*)(wr + 32);
                ulonglong2 wd = *(const ulonglong2*)(wr + 48);
#pragma unroll
                for (int qq = 0; qq < 2; qq++) {
                    m2[qq][0] = fma2(V[qq][fi], wa.x, m2[qq][0]);
                    m2[qq][1] = fma2(V[qq][fi], wa.y, m2[qq][1]);
                    m2[qq][2] = fma2(V[qq][fi], wb.x, m2[qq][2]);
                    m2[qq][3] = fma2(V[qq][fi], wb.y, m2[qq][3]);
                    m2[qq][4] = fma2(V[qq][fi], wc.x, m2[qq][4]);
                    m2[qq][5] = fma2(V[qq][fi], wc.y, m2[qq][5]);
                    m2[qq][6] = fma2(V[qq][fi], wd.x, m2[qq][6]);
                    m2[qq][7] = fma2(V[qq][fi], wd.y, m2[qq][7]);
                }
            }
#pragma unroll
            for (int qq = 0; qq < 2; qq++)
#pragma unroll
                for (int f = 0; f < 8; f++) {
                    float a, b2;
                    upk2(m2[qq][f], a, b2);
                    m2[qq][f] = pk2(leaky(a), leaky(b2));
                }
            const char* wbase2 = wbase + 512;
            uint64_t o2[2][8];
#pragma unroll
            for (int qq = 0; qq < 2; qq++)
#pragma unroll
                for (int f = 0; f < 8; f++) o2[qq][f] = 0ull;
#pragma unroll
            for (int fi = 0; fi < 8; fi++) {
                const char* wr = wbase2 + fi * 64;
                ulonglong2 wa = *(const ulonglong2*)(wr);
                ulonglong2 wb = *(const ulonglong2*)(wr + 16);
                ulonglong2 wc = *(const ulonglong2*)(wr + 32);
                ulonglong2 wd = *(const ulonglong2*)(wr + 48);
#pragma unroll
                for (int qq = 0; qq < 2; qq++) {
                    o2[qq][0] = fma2(m2[qq][fi], wa.x, o2[qq][0]);
                    o2[qq][1] = fma2(m2[qq][fi], wa.y, o2[qq][1]);
                    o2[qq][2] = fma2(m2[qq][fi], wb.x, o2[qq][2]);
                    o2[qq][3] = fma2(m2[qq][fi], wb.y, o2[qq][3]);
                    o2[qq][4] = fma2(m2[qq][fi], wc.x, o2[qq][4]);
                    o2[qq][5] = fma2(m2[qq][fi], wc.y, o2[qq][5]);
                    o2[qq][6] = fma2(m2[qq][fi], wd.x, o2[qq][6]);
                    o2[qq][7] = fma2(m2[qq][fi], wd.y, o2[qq][7]);
                }
            }
#pragma unroll
            for (int qq = 0; qq < 2; qq++) {
                const int ca = c0 + (2 * qq) * 4;
                const int cb2 = c0 + (2 * qq + 1) * 4;
#pragma unroll
                for (int f = 0; f < 8; f++) {
                    float x0, x1;
                    upk2(o2[qq][f], x0, x1);
                    __nv_bfloat16 h0 = __float2bfloat16(x0);
                    __nv_bfloat16 l0 = __float2bfloat16(x0 - __bfloat162float(h0));
                    uint32_t oA = SW128((uint32_t)((ca * 8 + f) * 128 + nn * 2));
                    *(__nv_bfloat16*)(sm + OFF_THI + oA) = h0;
                    *(__nv_bfloat16*)(sm + OFF_TLO + oA) = l0;
                    __nv_bfloat16 h1 = __float2bfloat16(x1);
                    __nv_bfloat16 l1 = __float2bfloat16(x1 - __bfloat162float(h1));
                    uint32_t oB = SW128((uint32_t)((cb2 * 8 + f) * 128 + nn * 2));
                    *(__nv_bfloat16*)(sm + OFF_THI + oB) = h1;
                    *(__nv_bfloat16*)(sm + OFF_TLO + oB) = l1;
                }
            }
        }
        __syncthreads();

        warp_app<true>(smb, sm, Uf, OFF_THI, OFF_TLO, wid, lane);
        __syncwarp();
        __syncthreads();
    }

    // ---- tail: t[m][c] = sum_f X[(c,f)][m]*tw[f] -> bf16 split B operand ----
#pragma unroll
    for (int p = 0; p < 4; p++) {
        int idx = tid + p * 256;
        int m = idx & 63, c = idx >> 6;
        float s = 0.f;
#pragma unroll
        for (int f = 0; f < 8; f++) {
            uint32_t off = SW128((uint32_t)((c * 8 + f) * 128 + m * 2));
            float xv = __bfloat162float(*(__nv_bfloat16*)(sm + OFF_XHI + off))
                     + __bfloat162float(*(__nv_bfloat16*)(sm + OFF_XLO + off));
            s = fmaf(xv, WB[8 + f], s);
        }
        __nv_bfloat16 h = __float2bfloat16(s);
        __nv_bfloat16 l = __float2bfloat16(s - __bfloat162float(h));
        uint32_t o = SW128((uint32_t)(c * 128 + m * 2));
        *(__nv_bfloat16*)(sm + OFF_FBH + o) = h;
        *(__nv_bfloat16*)(sm + OFF_FBL + o) = l;
    }
    __syncthreads();

    // out = leaky(adj @ t) via small MMA, straight to gout
    {
        float ch[4];
        small_mma(smb, wid, lane, ch);
        const int rg = lane >> 2, cg = (lane & 3) * 2;
        const int col = (wid >> 2) * 8 + cg;
        const int row = (wid & 3) * 16 + rg;
        *(float2*)&gout[row * 64 + col] = make_float2(leaky(ch[0]), leaky(ch[1]));
        *(float2*)&gout[(row + 8) * 64 + col] = make_float2(leaky(ch[2]), leaky(ch[3]));
    }
}

// ============================================================================
// Kernel 3: gather + fuse 1x1 conv + bias + residual (FFMA2 GEMM loop)
// ============================================================================
__global__ __launch_bounds__(256) void k_fuse(
    const float* __restrict__ x, const float* __restrict__ fuse_w,
    const float* __restrict__ fuse_b, float* __restrict__ out)
{
    extern __shared__ float sm_fuse[];
    float* as = sm_fuse;
    float* ws = sm_fuse + 128 * 68;
    const int tid = threadIdx.x;
    const int b = blockIdx.x >> 6, h = blockIdx.x & 63;

    const float* gh = g_gout[0] + (size_t)blockIdx.x * 4096;
    for (int i = tid; i < 4096; i += 256) {
        int w = i >> 6, c = i & 63;
        as[c * 68 + w] = gh[i];
    }
    const float* gvbase = g_gout[1] + (size_t)b * 64 * 4096 + h * 64;
    for (int i = tid; i < 4096; i += 256) {
        int w = i >> 6, c = i & 63;
        as[(64 + c) * 68 + w] = gvbase[(size_t)w * 4096 + c];
    }
    for (int i = tid; i < 128 * 128; i += 256) {
        int oc = i >> 7, c = i & 127;
        ws[c * 132 + oc] = fuse_w[i];
    }
    __syncthreads();

    const int oc0 = (tid >> 4) * 8;
    const int w0 = (tid & 15) * 4;
    uint64_t acc2[16];
#pragma unroll
    for (int i = 0; i < 16; i++) acc2[i] = 0ull;
#pragma unroll 4
    for (int c = 0; c < 128; c++) {
        float4 a0 = *(const float4*)(ws + c * 132 + oc0);
        float4 a1 = *(const float4*)(ws + c * 132 + oc0 + 4);
        ulonglong2 bv = *(const ulonglong2*)(as + c * 68 + w0);
        uint64_t d;
        d = pk2(a0.x, a0.x); acc2[0]  = fma2(d, bv.x, acc2[0]);  acc2[1]  = fma2(d, bv.y, acc2[1]);
        d = pk2(a0.y, a0.y); acc2[2]  = fma2(d, bv.x, acc2[2]);  acc2[3]  = fma2(d, bv.y, acc2[3]);
        d = pk2(a0.z, a0.z); acc2[4]  = fma2(d, bv.x, acc2[4]);  acc2[5]  = fma2(d, bv.y, acc2[5]);
        d = pk2(a0.w, a0.w); acc2[6]  = fma2(d, bv.x, acc2[6]);  acc2[7]  = fma2(d, bv.y, acc2[7]);
        d = pk2(a1.x, a1.x); acc2[8]  = fma2(d, bv.x, acc2[8]);  acc2[9]  = fma2(d, bv.y, acc2[9]);
        d = pk2(a1.y, a1.y); acc2[10] = fma2(d, bv.x, acc2[10]); acc2[11] = fma2(d, bv.y, acc2[11]);
        d = pk2(a1.z, a1.z); acc2[12] = fma2(d, bv.x, acc2[12]); acc2[13] = fma2(d, bv.y, acc2[13]);
        d = pk2(a1.w, a1.w); acc2[14] = fma2(d, bv.x, acc2[14]); acc2[15] = fma2(d, bv.y, acc2[15]);
    }
    const float* xblk = x + (size_t)b * 128 * 4096 + h * 64;
    float* oblk = out + (size_t)b * 128 * 4096 + h * 64;
#pragma unroll
    for (int i = 0; i < 8; i++) {
        int oc = oc0 + i;
        float bia = fuse_b[oc];
        float v0, v1, v2, v3;
        upk2(acc2[2 * i], v0, v1);
        upk2(acc2[2 * i + 1], v2, v3);
        float4 xv = *(const float4*)(xblk + (size_t)oc * 4096 + w0);
        *(float4*)(oblk + (size_t)oc * 4096 + w0) =
            make_float4(v0 + bia + xv.x, v1 + bia + xv.y,
                        v2 + bia + xv.z, v3 + bia + xv.w);
    }
}

extern "C" void kernel_launch(void* const* d_in, const int* in_sizes, int n_in,
                              void* d_out, int out_size)
{
    const float* x      = (const float*)d_in[0];
    const float* adj_h  = (const float*)d_in[1];
    const float* adj_v  = (const float*)d_in[2];
    const float* norm_w = (const float*)d_in[3];
    const float* norm_b = (const float*)d_in[4];
    const float* conv_w = (const float*)d_in[5];
    const float* conv_b = (const float*)d_in[6];
    const float* fuse_w = (const float*)d_in[7];
    const float* fuse_b = (const float*)d_in[8];
    const float* head_h = (const float*)d_in[9];
    const float* tail_h = (const float*)d_in[10];
    const float* w1_h   = (const float*)d_in[11];
    const float* w2_h   = (const float*)d_in[12];
    const float* head_v = (const float*)d_in[13];
    const float* tail_v = (const float*)d_in[14];
    const float* w1_v   = (const float*)d_in[15];
    const float* w2_v   = (const float*)d_in[16];
    float* out = (float*)d_out;

    const size_t s_pre  = (size_t)(128 * 64 + 128 * 132 + 128) * sizeof(float);
    const size_t s_fuse = (size_t)(128 * 68 + 128 * 132) * sizeof(float);
    cudaFuncSetAttribute(k_pre, cudaFuncAttributeMaxDynamicSharedMemorySize, (int)s_pre);
    cudaFuncSetAttribute(k_gcm, cudaFuncAttributeMaxDynamicSharedMemorySize, (int)GCM_SMEM);
    cudaFuncSetAttribute(k_fuse, cudaFuncAttributeMaxDynamicSharedMemorySize, (int)s_fuse);

    k_pre<<<256, 256, s_pre>>>(x, norm_w, norm_b, conv_w, conv_b);
    k_gcm<<<dim3(256, 4, 2), 256, GCM_SMEM>>>(adj_h, adj_v, head_h, tail_h, w1_h, w2_h,
                                              head_v, tail_v, w1_v, w2_v);
    k_fuse<<<256, 256, s_fuse>>>(x, fuse_w, fuse_b, out);
}

// round 14
// speedup vs baseline: 1.0683x; 1.0071x over previous
#include <cuda_runtime.h>
#include <cuda_bf16.h>
#include <cstdint>

#define LRELU_SLOPE 0.2f

// Scratch: [dir][graph(256)][node(64)][ch(64)]
__device__ float g_feat[2][256 * 64 * 64];
__device__ float g_gout[2][256 * 64 * 64];

__device__ __forceinline__ float leaky(float v) { return v >= 0.f ? v : LRELU_SLOPE * v; }

// ---- packed f32x2 helpers ----
__device__ __forceinline__ uint64_t pk2(float x, float y) {
    uint64_t r; asm("mov.b64 %0, {%1, %2};" : "=l"(r) : "f"(x), "f"(y)); return r;
}
__device__ __forceinline__ void upk2(uint64_t v, float& x, float& y) {
    asm("mov.b64 {%0, %1}, %2;" : "=f"(x), "=f"(y) : "l"(v));
}
__device__ __forceinline__ uint64_t fma2(uint64_t a, uint64_t b, uint64_t c) {
    uint64_t d; asm("fma.rn.f32x2 %0, %1, %2, %3;" : "=l"(d) : "l"(a), "l"(b), "l"(c)); return d;
}

__device__ __forceinline__ uint32_t smem_u32(const void* p) {
    uint32_t a;
    asm("{ .reg .u64 t; cvta.to.shared.u64 t, %1; cvt.u32.u64 %0, t; }" : "=r"(a) : "l"(p));
    return a;
}
#define SW128(o) ((o) ^ (((o) >> 3) & 0x70))

__device__ __forceinline__ void ldsm4(uint32_t r[4], uint32_t addr) {
    asm volatile("ldmatrix.sync.aligned.m8n8.x4.shared.b16 {%0,%1,%2,%3}, [%4];"
                 : "=r"(r[0]), "=r"(r[1]), "=r"(r[2]), "=r"(r[3]) : "r"(addr));
}
__device__ __forceinline__ void mma16816(float c[4], const uint32_t a[4], uint32_t b0, uint32_t b1) {
    asm volatile(
        "mma.sync.aligned.m16n8k16.row.col.f32.bf16.bf16.f32 "
        "{%0,%1,%2,%3}, {%4,%5,%6,%7}, {%8,%9}, {%0,%1,%2,%3};"
        : "+f"(c[0]), "+f"(c[1]), "+f"(c[2]), "+f"(c[3])
        : "r"(a[0]), "r"(a[1]), "r"(a[2]), "r"(a[3]), "r"(b0), "r"(b1));
}

// ============================================================================
// Kernel 1: LayerNorm + 1x1 conv + leaky + strip split (FFMA2 GEMM loop)
// ============================================================================
__global__ __launch_bounds__(256) void k_pre(
    const float* __restrict__ x, const float* __restrict__ norm_w,
    const float* __restrict__ norm_b, const float* __restrict__ conv_w,
    const float* __restrict__ conv_b)
{
    extern __shared__ float sm_pre[];
    float* xs = sm_pre;
    float* ws = sm_pre + 128 * 64;
    float* mu = ws + 128 * 132;
    float* rs = mu + 64;
    const int tid = threadIdx.x;
    const int b = blockIdx.x >> 6, h = blockIdx.x & 63;
    const float* xblk = x + (size_t)b * 128 * 4096 + h * 64;

    for (int i = tid; i < 128 * 64; i += 256) {
        int c = i >> 6, w = i & 63;
        xs[i] = xblk[c * 4096 + w];
    }
    for (int i = tid; i < 128 * 128; i += 256) {
        int oc = i >> 7, c = i & 127;
        ws[c * 132 + oc] = conv_w[i];
    }
    __syncthreads();
    if (tid < 64) {
        float s = 0.f, s2 = 0.f;
#pragma unroll 8
        for (int c = 0; c < 128; c++) { float v = xs[c * 64 + tid]; s += v; s2 += v * v; }
        float m = s * 0.0078125f;
        float var = s2 * 0.0078125f - m * m;
        mu[tid] = m; rs[tid] = rsqrtf(var + 1e-5f);
    }
    __syncthreads();
    for (int i = tid; i < 128 * 64; i += 256) {
        int c = i >> 6, w = i & 63;
        xs[i] = (xs[i] - mu[w]) * rs[w] * norm_w[c] + norm_b[c];
    }
    __syncthreads();

    const int oc0 = (tid >> 4) * 8;
    const int w0 = (tid & 15) * 4;
    uint64_t acc2[16];
#pragma unroll
    for (int i = 0; i < 16; i++) acc2[i] = 0ull;
#pragma unroll 4
    for (int c = 0; c < 128; c++) {
        float4 a0 = *(const float4*)(ws + c * 132 + oc0);
        float4 a1 = *(const float4*)(ws + c * 132 + oc0 + 4);
        ulonglong2 bv = *(const ulonglong2*)(xs + c * 64 + w0);
        uint64_t d;
        d = pk2(a0.x, a0.x); acc2[0]  = fma2(d, bv.x, acc2[0]);  acc2[1]  = fma2(d, bv.y, acc2[1]);
        d = pk2(a0.y, a0.y); acc2[2]  = fma2(d, bv.x, acc2[2]);  acc2[3]  = fma2(d, bv.y, acc2[3]);
        d = pk2(a0.z, a0.z); acc2[4]  = fma2(d, bv.x, acc2[4]);  acc2[5]  = fma2(d, bv.y, acc2[5]);
        d = pk2(a0.w, a0.w); acc2[6]  = fma2(d, bv.x, acc2[6]);  acc2[7]  = fma2(d, bv.y, acc2[7]);
        d = pk2(a1.x, a1.x); acc2[8]  = fma2(d, bv.x, acc2[8]);  acc2[9]  = fma2(d, bv.y, acc2[9]);
        d = pk2(a1.y, a1.y); acc2[10] = fma2(d, bv.x, acc2[10]); acc2[11] = fma2(d, bv.y, acc2[11]);
        d = pk2(a1.z, a1.z); acc2[12] = fma2(d, bv.x, acc2[12]); acc2[13] = fma2(d, bv.y, acc2[13]);
        d = pk2(a1.w, a1.w); acc2[14] = fma2(d, bv.x, acc2[14]); acc2[15] = fma2(d, bv.y, acc2[15]);
    }
    float av[8][4];
#pragma unroll
    for (int i = 0; i < 8; i++) {
        upk2(acc2[2 * i], av[i][0], av[i][1]);
        upk2(acc2[2 * i + 1], av[i][2], av[i][3]);
        float bia = conv_b[oc0 + i];
#pragma unroll
        for (int j = 0; j < 4; j++) av[i][j] = leaky(av[i][j] + bia);
    }
    if (oc0 < 64) {
#pragma unroll
        for (int j = 0; j < 4; j++) {
            int w = w0 + j;
            float* dst = g_feat[0] + ((size_t)blockIdx.x * 64 + w) * 64 + oc0;
            *(float4*)dst = make_float4(av[0][j], av[1][j], av[2][j], av[3][j]);
            *(float4*)(dst + 4) = make_float4(av[4][j], av[5][j], av[6][j], av[7][j]);
        }
    } else {
#pragma unroll
        for (int j = 0; j < 4; j++) {
            int w = w0 + j;
            float* dst = g_feat[1] + ((size_t)(b * 64 + w) * 64 + h) * 64 + (oc0 - 64);
            *(float4*)dst = make_float4(av[0][j], av[1][j], av[2][j], av[3][j]);
            *(float4*)(dst + 4) = make_float4(av[4][j], av[5][j], av[6][j], av[7][j]);
        }
    }
}

// ============================================================================
// GCM via warp-level mma.sync bf16 3-term split. CH-TILE = 16, 2 CTAs/SM.
// Head and tail adj-GEMMs also on MMA (B = 16-row operand in T region).
// fmix uses node-pair f32x2 packing (contiguous loads/stores).
// ============================================================================
#define OFF_AHI 0u
#define OFF_ALO 8192u
#define OFF_XHI 16384u
#define OFF_XLO 32768u
#define OFF_THI 49152u
#define OFF_TLO 65536u
#define OFF_U   49152u
#define OFF_FBH 49152u            // 16-row B operand hi (head: feat^T, tail: t^T)
#define OFF_FBL 51200u            // 16-row B operand lo
#define OFF_GS  57344u            // gS fp32 [64][18] (head output)
#define OFF_WB  83968u
#define OFF_W2B 86080u
#define GCM_SMEM 90176u

template <bool RESID>
__device__ __forceinline__ void warp_app(uint32_t smb, char* smc, float* __restrict__ Uf,
                                         uint32_t aHiOff, uint32_t aLoOff,
                                         int wid, int lane)
{
    float c[8][4];
#pragma unroll
    for (int nt = 0; nt < 8; nt++)
#pragma unroll
        for (int j = 0; j < 4; j++) c[nt][j] = 0.f;

    const int warpM = wid * 16;
    const uint32_t aRow = warpM + (lane & 15);
    const uint32_t aK8 = (lane >> 4) * 8;
    const int q = lane >> 3;
    const uint32_t bRow = (lane & 7) + ((q >> 1) * 8);
    const uint32_t bK8 = (q & 1) * 8;

#pragma unroll
    for (int ks = 0; ks < 4; ks++) {
        const uint32_t ao = SW128(aRow * 128 + (ks * 16 + aK8) * 2);
        uint32_t aH[4], aL[4];
        ldsm4(aH, smb + aHiOff + ao);
        ldsm4(aL, smb + aLoOff + ao);
#pragma unroll
        for (int nt2 = 0; nt2 < 4; nt2++) {
            const uint32_t bo = SW128((nt2 * 16 + bRow) * 128 + (ks * 16 + bK8) * 2);
            uint32_t bH[4], bL[4];
            ldsm4(bH, smb + OFF_AHI + bo);
            ldsm4(bL, smb + OFF_ALO + bo);
            mma16816(c[nt2 * 2 + 0], aH, bH[0], bH[1]);
            mma16816(c[nt2 * 2 + 1], aH, bH[2], bH[3]);
            mma16816(c[nt2 * 2 + 0], aH, bL[0], bL[1]);
            mma16816(c[nt2 * 2 + 1], aH, bL[2], bL[3]);
            mma16816(c[nt2 * 2 + 0], aL, bH[0], bH[1]);
            mma16816(c[nt2 * 2 + 1], aL, bH[2], bH[3]);
        }
    }

    const int rg = lane >> 2, cg = (lane & 3) * 2;
    if (!RESID) {
#pragma unroll
        for (int nt = 0; nt < 8; nt++) {
            const int col = nt * 8 + cg;
            const int row0 = warpM + rg;
            *(float2*)&Uf[row0 * 68 + col] = make_float2(c[nt][0], c[nt][1]);
            *(float2*)&Uf[(row0 + 8) * 68 + col] = make_float2(c[nt][2], c[nt][3]);
        }
    } else {
#pragma unroll
        for (int nt = 0; nt < 8; nt++) {
            const int col = nt * 8 + cg;
#pragma unroll
            for (int hh = 0; hh < 2; hh++) {
                const int row = warpM + rg + hh * 8;
                const uint32_t off = SW128((uint32_t)(row * 128 + col * 2));
                __nv_bfloat162 h2 = *(__nv_bfloat162*)(smc + OFF_XHI + off);
                __nv_bfloat162 l2 = *(__nv_bfloat162*)(smc + OFF_XLO + off);
                float x0 = __bfloat162float(h2.x) + __bfloat162float(l2.x) + c[nt][hh * 2];
                float x1 = __bfloat162float(h2.y) + __bfloat162float(l2.y) + c[nt][hh * 2 + 1];
                __nv_bfloat16 nh0 = __float2bfloat16(x0);
                __nv_bfloat16 nl0 = __float2bfloat16(x0 - __bfloat162float(nh0));
                __nv_bfloat16 nh1 = __float2bfloat16(x1);
                __nv_bfloat16 nl1 = __float2bfloat16(x1 - __bfloat162float(nh1));
                __nv_bfloat162 oh; oh.x = nh0; oh.y = nh1;
                __nv_bfloat162 ol; ol.x = nl0; ol.y = nl1;
                *(__nv_bfloat162*)(smc + OFF_XHI + off) = oh;
                *(__nv_bfloat162*)(smc + OFF_XLO + off) = ol;
            }
        }
    }
}

// Small MMA: D[64 l][16 c] = adj @ B16, 3-term split. Warp w: m-tile (w&3), n-tile (w>>2).
__device__ __forceinline__ void small_mma(uint32_t smb, int wid, int lane, float ch[4])
{
    const int hwM = (wid & 3) * 16;
    const int hnt = wid >> 2;
    const uint32_t aRow = hwM + (lane & 15);
    const uint32_t aK8 = (lane >> 4) * 8;
    const int q = lane >> 3;
    const uint32_t bRow = (lane & 7) + ((q >> 1) * 8);
    const uint32_t bK8 = (q & 1) * 8;
    ch[0] = ch[1] = ch[2] = ch[3] = 0.f;
#pragma unroll
    for (int ks = 0; ks < 4; ks++) {
        uint32_t ao = SW128(aRow * 128 + (ks * 16 + aK8) * 2);
        uint32_t aH[4], aL[4];
        ldsm4(aH, smb + OFF_AHI + ao);
        ldsm4(aL, smb + OFF_ALO + ao);
        uint32_t bo = SW128(bRow * 128 + (ks * 16 + bK8) * 2);
        uint32_t bH[4], bL[4];
        ldsm4(bH, smb + OFF_FBH + bo);
        ldsm4(bL, smb + OFF_FBL + bo);
        uint32_t b0H = hnt ? bH[2] : bH[0], b1H = hnt ? bH[3] : bH[1];
        uint32_t b0L = hnt ? bL[2] : bL[0], b1L = hnt ? bL[3] : bL[1];
        mma16816(ch, aH, b0H, b1H);
        mma16816(ch, aH, b0L, b1L);
        mma16816(ch, aL, b0H, b1H);
    }
}

__device__ __forceinline__ void store_row_split32(char* smc, uint32_t hiOff, uint32_t loOff,
                                                  int r, int cb, const float* v) {
    const uint32_t rowb = (uint32_t)r * 128;
#pragma unroll
    for (int j = 0; j < 32; j += 8) {
        ushort hi[8], lo[8];
#pragma unroll
        for (int qq = 0; qq < 8; qq++) {
            float x = v[j + qq];
            __nv_bfloat16 h = __float2bfloat16(x);
            __nv_bfloat16 l = __float2bfloat16(x - __bfloat162float(h));
            hi[qq] = *(ushort*)&h; lo[qq] = *(ushort*)&l;
        }
        uint32_t o = SW128(rowb + (cb + j) * 2);
        *(uint4*)(smc + hiOff + o) = *(uint4*)hi;
        *(uint4*)(smc + loOff + o) = *(uint4*)lo;
    }
}

__global__ __launch_bounds__(256, 2) void k_gcm(
    const float* __restrict__ adj_h, const float* __restrict__ adj_v,
    const float* __restrict__ head_h, const float* __restrict__ tail_h,
    const float* __restrict__ w1_h, const float* __restrict__ w2_h,
    const float* __restrict__ head_v, const float* __restrict__ tail_v,
    const float* __restrict__ w1_v, const float* __restrict__ w2_v)
{
    extern __shared__ __align__(1024) char sm[];
    const uint32_t smb = smem_u32(sm);
    float* Uf = (float*)(sm + OFF_U);
    float* WB = (float*)(sm + OFF_WB);
    float* gS = (float*)(sm + OFF_GS);
    const int tid = threadIdx.x;
    const int wid = tid >> 5, lane = tid & 31;
    const int graph = blockIdx.x, ct = blockIdx.y, dir = blockIdx.z;
    const float* adj = dir ? adj_v : adj_h;
    const float* hw = dir ? head_v : head_h;
    const float* tw = dir ? tail_v : tail_h;
    const float* w1 = dir ? w1_v : w1_h;
    const float* w2 = dir ? w2_v : w2_h;
    const float* feat = g_feat[dir] + (size_t)graph * 4096 + ct * 16;
    float* gout = g_gout[dir] + (size_t)graph * 4096 + ct * 16;

    // ---- stage adj bf16 hi/lo (vectorized: 8 contiguous m per item) ----
    for (int i = tid; i < 512; i += 256) {
        const int l = i >> 3, mb = (i & 7) * 8;
        float4 v0 = *(const float4*)(adj + l * 64 + mb);
        float4 v1 = *(const float4*)(adj + l * 64 + mb + 4);
        float vv[8] = {v0.x, v0.y, v0.z, v0.w, v1.x, v1.y, v1.z, v1.w};
        ushort hi[8], lo[8];
#pragma unroll
        for (int qq = 0; qq < 8; qq++) {
            __nv_bfloat16 h = __float2bfloat16(vv[qq]);
            __nv_bfloat16 ll = __float2bfloat16(vv[qq] - __bfloat162float(h));
            hi[qq] = *(ushort*)&h; lo[qq] = *(ushort*)&ll;
        }
        uint32_t o = SW128((uint32_t)(l * 128 + mb * 2));
        *(uint4*)(sm + OFF_AHI + o) = *(uint4*)hi;
        *(uint4*)(sm + OFF_ALO + o) = *(uint4*)lo;
    }
    for (int i = tid; i < 1024; i += 256) {
        int m = i >> 4, c = i & 15;
        float v = feat[m * 64 + c];
        __nv_bfloat16 h = __float2bfloat16(v);
        __nv_bfloat16 lo = __float2bfloat16(v - __bfloat162float(h));
        uint32_t o = SW128((uint32_t)(c * 128 + m * 2));
        *(__nv_bfloat16*)(sm + OFF_FBH + o) = h;
        *(__nv_bfloat16*)(sm + OFF_FBL + o) = lo;
    }
    for (int i = tid; i < 528; i += 256) {
        float v;
        if (i < 8) v = hw[i];
        else if (i < 16) v = tw[i - 8];
        else if (i < 272) v = w1[i - 16];
        else v = w2[i - 272];
        WB[i] = v;
    }
    for (int i = tid; i < 512; i += 256) {
        int it = i >> 7, rest = i & 127;
        int s = rest >> 6, idx = rest & 63;
        float v = s ? w2[it * 64 + idx] : w1[it * 64 + idx];
        *(float2*)(sm + OFF_W2B + (size_t)i * 8) = make_float2(v, v);
    }
    __syncthreads();

    // ---- head: g = adj @ feat via small MMA ----
    {
        float ch[4];
        small_mma(smb, wid, lane, ch);
        const int rg = lane >> 2, cg = (lane & 3) * 2;
        const int col = (wid >> 2) * 8 + cg;
        const int row = (wid & 3) * 16 + rg;
        *(float2*)&gS[row * 18 + col] = make_float2(ch[0], ch[1]);
        *(float2*)&gS[(row + 8) * 18 + col] = make_float2(ch[2], ch[3]);
    }
    __syncthreads();

    // X[r][l] = g[l][c] * hw[f]  -> XHI/XLO
    {
        const int r = tid >> 1, half = tid & 1;
        const int c = r >> 3, f = r & 7;
        const float hf = WB[f];
        const int cb = half * 32;
        float v[32];
#pragma unroll
        for (int l = 0; l < 32; l++) v[l] = gS[(cb + l) * 18 + c] * hf;
        store_row_split32(sm, OFF_XHI, OFF_XLO, r, cb, v);
    }
    __syncthreads();

    // ---- ResGCN body ----
    for (int it = 0; it < 4; it++) {
        warp_app<false>(smb, sm, Uf, OFF_XHI, OFF_XLO, wid, lane);
        __syncthreads();

        // fmix: T = leaky(U W1) W2 -> THI/TLO (node-pair packed f32x2)
        {
            // channels {wid, wid+8}, nodes {2*lane, 2*lane+1}
            uint64_t V[2][8];
#pragma unroll
            for (int ci = 0; ci < 2; ci++) {
                const int c = wid + ci * 8;
#pragma unroll
                for (int f = 0; f < 8; f++) {
                    float2 v2 = *(const float2*)&Uf[(c * 8 + f) * 68 + 2 * lane];
                    V[ci][f] = pk2(v2.x, v2.y);
                }
            }
            __syncthreads();  // Uf reads done before T writes (alias)

            const char* wbase = sm + OFF_W2B + it * 1024;
            uint64_t m2[2][8];
#pragma unroll
            for (int ci = 0; ci < 2; ci++)
#pragma unroll
                for (int f = 0; f < 8; f++) m2[ci][f] = 0ull;
#pragma unroll
            for (int fi = 0; fi < 8; fi++) {
                const char* wr = wbase + fi * 64;
                ulonglong2 wa = *(const ulonglong2*)(wr);
                ulonglong2 wb = *(const ulonglong2*)(wr + 16);
                ulonglong2 wc = *(const ulonglong2*)(wr + 32);
                ulonglong2 wd = *(const ulonglong2*)(wr + 48);
#pragma unroll
                for (int ci = 0; ci < 2; ci++) {
                    m2[ci][0] = fma2(V[ci][fi], wa.x, m2[ci][0]);
                    m2[ci][1] = fma2(V[ci][fi], wa.y, m2[ci][1]);
                    m2[ci][2] = fma2(V[ci][fi], wb.x, m2[ci][2]);
                    m2[ci][3] = fma2(V[ci][fi], wb.y, m2[ci][3]);
                    m2[ci][4] = fma2(V[ci][fi], wc.x, m2[ci][4]);
                    m2[ci][5] = fma2(V[ci][fi], wc.y, m2[ci][5]);
                    m2[ci][6] = fma2(V[ci][fi], wd.x, m2[ci][6]);
                    m2[ci][7] = fma2(V[ci][fi], wd.y, m2[ci][7]);
                }
            }
#pragma unroll
            for (int ci = 0; ci < 2; ci++)
#pragma unroll
                for (int f = 0; f < 8; f++) {
                    float a, b2;
                    upk2(m2[ci][f], a, b2);
                    m2[ci][f] = pk2(leaky(a), leaky(b2));
                }
            const char* wbase2 = wbase + 512;
            uint64_t o2[2][8];
#pragma unroll
            for (int ci = 0; ci < 2; ci++)
#pragma unroll
                for (int f = 0; f < 8; f++) o2[ci][f] = 0ull;
#pragma unroll
            for (int fi = 0; fi < 8; fi++) {
                const char* wr = wbase2 + fi * 64;
                ulonglong2 wa = *(const ulonglong2*)(wr);
                ulonglong2 wb = *(const ulonglong2*)(wr + 16);
                ulonglong2 wc = *(const ulonglong2*)(wr + 32);
                ulonglong2 wd = *(const ulonglong2*)(wr + 48);
#pragma unroll
                for (int ci = 0; ci < 2; ci++) {
                    o2[ci][0] = fma2(m2[ci][fi], wa.x, o2[ci][0]);
                    o2[ci][1] = fma2(m2[ci][fi], wa.y, o2[ci][1]);
                    o2[ci][2] = fma2(m2[ci][fi], wb.x, o2[ci][2]);
                    o2[ci][3] = fma2(m2[ci][fi], wb.y, o2[ci][3]);
                    o2[ci][4] = fma2(m2[ci][fi], wc.x, o2[ci][4]);
                    o2[ci][5] = fma2(m2[ci][fi], wc.y, o2[ci][5]);
                    o2[ci][6] = fma2(m2[ci][fi], wd.x, o2[ci][6]);
                    o2[ci][7] = fma2(m2[ci][fi], wd.y, o2[ci][7]);
                }
            }
            // store node-pair bf16x2 (4 B per buffer)
#pragma unroll
            for (int ci = 0; ci < 2; ci++) {
                const int c = wid + ci * 8;
#pragma unroll
                for (int f = 0; f < 8; f++) {
                    float x0, x1;
                    upk2(o2[ci][f], x0, x1);
                    __nv_bfloat16 h0 = __float2bfloat16(x0);
                    __nv_bfloat16 l0 = __float2bfloat16(x0 - __bfloat162float(h0));
                    __nv_bfloat16 h1 = __float2bfloat16(x1);
                    __nv_bfloat16 l1 = __float2bfloat16(x1 - __bfloat162float(h1));
                    __nv_bfloat162 hh; hh.x = h0; hh.y = h1;
                    __nv_bfloat162 ll; ll.x = l0; ll.y = l1;
                    uint32_t o = SW128((uint32_t)((c * 8 + f) * 128 + lane * 4));
                    *(__nv_bfloat162*)(sm + OFF_THI + o) = hh;
                    *(__nv_bfloat162*)(sm + OFF_TLO + o) = ll;
                }
            }
        }
        __syncthreads();

        warp_app<true>(smb, sm, Uf, OFF_THI, OFF_TLO, wid, lane);
        __syncthreads();
    }

    // ---- tail: t[m][c] = sum_f X[(c,f)][m]*tw[f] -> bf16 split B operand ----
#pragma unroll
    for (int p = 0; p < 4; p++) {
        int idx = tid + p * 256;
        int m = idx & 63, c = idx >> 6;
        float s = 0.f;
#pragma unroll
        for (int f = 0; f < 8; f++) {
            uint32_t off = SW128((uint32_t)((c * 8 + f) * 128 + m * 2));
            float xv = __bfloat162float(*(__nv_bfloat16*)(sm + OFF_XHI + off))
                     + __bfloat162float(*(__nv_bfloat16*)(sm + OFF_XLO + off));
            s = fmaf(xv, WB[8 + f], s);
        }
        __nv_bfloat16 h = __float2bfloat16(s);
        __nv_bfloat16 l = __float2bfloat16(s - __bfloat162float(h));
        uint32_t o = SW128((uint32_t)(c * 128 + m * 2));
        *(__nv_bfloat16*)(sm + OFF_FBH + o) = h;
        *(__nv_bfloat16*)(sm + OFF_FBL + o) = l;
    }
    __syncthreads();

    // out = leaky(adj @ t) via small MMA, straight to gout
    {
        float ch[4];
        small_mma(smb, wid, lane, ch);
        const int rg = lane >> 2, cg = (lane & 3) * 2;
        const int col = (wid >> 2) * 8 + cg;
        const int row = (wid & 3) * 16 + rg;
        *(float2*)&gout[row * 64 + col] = make_float2(leaky(ch[0]), leaky(ch[1]));
        *(float2*)&gout[(row + 8) * 64 + col] = make_float2(leaky(ch[2]), leaky(ch[3]));
    }
}

// ============================================================================
// Kernel 3: gather + fuse 1x1 conv + bias + residual (FFMA2 GEMM loop)
// ============================================================================
__global__ __launch_bounds__(256) void k_fuse(
    const float* __restrict__ x, const float* __restrict__ fuse_w,
    const float* __restrict__ fuse_b, float* __restrict__ out)
{
    extern __shared__ float sm_fuse[];
    float* as = sm_fuse;
    float* ws = sm_fuse + 128 * 68;
    const int tid = threadIdx.x;
    const int b = blockIdx.x >> 6, h = blockIdx.x & 63;

    const float* gh = g_gout[0] + (size_t)blockIdx.x * 4096;
    for (int i = tid; i < 4096; i += 256) {
        int w = i >> 6, c = i & 63;
        as[c * 68 + w] = gh[i];
    }
    const float* gvbase = g_gout[1] + (size_t)b * 64 * 4096 + h * 64;
    for (int i = tid; i < 4096; i += 256) {
        int w = i >> 6, c = i & 63;
        as[(64 + c) * 68 + w] = gvbase[(size_t)w * 4096 + c];
    }
    for (int i = tid; i < 128 * 128; i += 256) {
        int oc = i >> 7, c = i & 127;
        ws[c * 132 + oc] = fuse_w[i];
    }
    __syncthreads();

    const int oc0 = (tid >> 4) * 8;
    const int w0 = (tid & 15) * 4;
    uint64_t acc2[16];
#pragma unroll
    for (int i = 0; i < 16; i++) acc2[i] = 0ull;
#pragma unroll 4
    for (int c = 0; c < 128; c++) {
        float4 a0 = *(const float4*)(ws + c * 132 + oc0);
        float4 a1 = *(const float4*)(ws + c * 132 + oc0 + 4);
        ulonglong2 bv = *(const ulonglong2*)(as + c * 68 + w0);
        uint64_t d;
        d = pk2(a0.x, a0.x); acc2[0]  = fma2(d, bv.x, acc2[0]);  acc2[1]  = fma2(d, bv.y, acc2[1]);
        d = pk2(a0.y, a0.y); acc2[2]  = fma2(d, bv.x, acc2[2]);  acc2[3]  = fma2(d, bv.y, acc2[3]);
        d = pk2(a0.z, a0.z); acc2[4]  = fma2(d, bv.x, acc2[4]);  acc2[5]  = fma2(d, bv.y, acc2[5]);
        d = pk2(a0.w, a0.w); acc2[6]  = fma2(d, bv.x, acc2[6]);  acc2[7]  = fma2(d, bv.y, acc2[7]);
        d = pk2(a1.x, a1.x); acc2[8]  = fma2(d, bv.x, acc2[8]);  acc2[9]  = fma2(d, bv.y, acc2[9]);
        d = pk2(a1.y, a1.y); acc2[10] = fma2(d, bv.x, acc2[10]); acc2[11] = fma2(d, bv.y, acc2[11]);
        d = pk2(a1.z, a1.z); acc2[12] = fma2(d, bv.x, acc2[12]); acc2[13] = fma2(d, bv.y, acc2[13]);
        d = pk2(a1.w, a1.w); acc2[14] = fma2(d, bv.x, acc2[14]); acc2[15] = fma2(d, bv.y, acc2[15]);
    }
    const float* xblk = x + (size_t)b * 128 * 4096 + h * 64;
    float* oblk = out + (size_t)b * 128 * 4096 + h * 64;
#pragma unroll
    for (int i = 0; i < 8; i++) {
        int oc = oc0 + i;
        float bia = fuse_b[oc];
        float v0, v1, v2, v3;
        upk2(acc2[2 * i], v0, v1);
        upk2(acc2[2 * i + 1], v2, v3);
        float4 xv = *(const float4*)(xblk + (size_t)oc * 4096 + w0);
        *(float4*)(oblk + (size_t)oc * 4096 + w0) =
            make_float4(v0 + bia + xv.x, v1 + bia + xv.y,
                        v2 + bia + xv.z, v3 + bia + xv.w);
    }
}

extern "C" void kernel_launch(void* const* d_in, const int* in_sizes, int n_in,
                              void* d_out, int out_size)
{
    const float* x      = (const float*)d_in[0];
    const float* adj_h  = (const float*)d_in[1];
    const float* adj_v  = (const float*)d_in[2];
    const float* norm_w = (const float*)d_in[3];
    const float* norm_b = (const float*)d_in[4];
    const float* conv_w = (const float*)d_in[5];
    const float* conv_b = (const float*)d_in[6];
    const float* fuse_w = (const float*)d_in[7];
    const float* fuse_b = (const float*)d_in[8];
    const float* head_h = (const float*)d_in[9];
    const float* tail_h = (const float*)d_in[10];
    const float* w1_h   = (const float*)d_in[11];
    const float* w2_h   = (const float*)d_in[12];
    const float* head_v = (const float*)d_in[13];
    const float* tail_v = (const float*)d_in[14];
    const float* w1_v   = (const float*)d_in[15];
    const float* w2_v   = (const float*)d_in[16];
    float* out = (float*)d_out;

    const size_t s_pre  = (size_t)(128 * 64 + 128 * 132 + 128) * sizeof(float);
    const size_t s_fuse = (size_t)(128 * 68 + 128 * 132) * sizeof(float);
    cudaFuncSetAttribute(k_pre, cudaFuncAttributeMaxDynamicSharedMemorySize, (int)s_pre);
    cudaFuncSetAttribute(k_gcm, cudaFuncAttributeMaxDynamicSharedMemorySize, (int)GCM_SMEM);
    cudaFuncSetAttribute(k_fuse, cudaFuncAttributeMaxDynamicSharedMemorySize, (int)s_fuse);

    k_pre<<<256, 256, s_pre>>>(x, norm_w, norm_b, conv_w, conv_b);
    k_gcm<<<dim3(256, 4, 2), 256, GCM_SMEM>>>(adj_h, adj_v, head_h, tail_h, w1_h, w2_h,
                                              head_v, tail_v, w1_v, w2_v);
    k_fuse<<<256, 256, s_fuse>>>(x, fuse_w, fuse_b, out);
}